// round 11
// baseline (speedup 1.0000x reference)
#include <cuda_runtime.h>
#include <math.h>

#define T256 256
#define T128 128

// ---------------- global scratch (static, no allocation) ----------------
static __device__ float  g_feat[64 * 243 * 64];   // (b*3+c)*81*64 + ch*64 + pix
static __device__ float2 g_xf  [192 * 1024];      // fft2(x) per (b,c)
static __device__ float2 g_u0f [1536 * 1024];     // fft2(|ifft2(xf*psi0)|) per (bc,t1)

__device__ __forceinline__ int brevn(int i, int bits) {
    return (int)(__brev((unsigned)i) >> (32 - bits));
}

// ---------------- serial register-resident radix-2 DIF FFT ----------------
template<int N, bool INV>
__device__ __forceinline__ void fft_serial(float2* v, const float2* __restrict__ tw) {
#pragma unroll
    for (int m = N; m >= 2; m >>= 1) {
        const int half = m >> 1, step = N / m;
#pragma unroll
        for (int k0 = 0; k0 < N; k0 += m) {
#pragma unroll
            for (int j = 0; j < half; j++) {
                const int lo = k0 + j, hi = lo + half;
                const float2 a = v[lo], b = v[hi];
                const float2 d = make_float2(a.x - b.x, a.y - b.y);
                v[lo] = make_float2(a.x + b.x, a.y + b.y);
                if (j == 0) {
                    v[hi] = d;
                } else if (j * step == N / 4) {
                    v[hi] = INV ? make_float2(-d.y, d.x) : make_float2(d.y, -d.x);
                } else {
                    const float2 w = tw[j * step];
                    const float ws = INV ? w.y : -w.y;
                    v[hi] = make_float2(d.x * w.x - d.y * ws, d.y * w.x + d.x * ws);
                }
            }
        }
    }
}

// ---------------- K1: packed-pair fft2(x) for two real images per warp; s0; out init ----------------
// grid = 48, block = 64 (2 warps). Warp w handles pair = blockIdx.x*2 + w,
// i.e. real tiles bcA = 2*pair, bcB = bcA+1 packed as re/im of ONE complex FFT.
// Unpack spectra via conjugate symmetry into g_xf; packed phi-tail gives both s0.
__global__ void __launch_bounds__(64)
k1_xf(const float* __restrict__ x, const float* __restrict__ phi,
      const float* __restrict__ bias, float* __restrict__ out) {
    __shared__ float2 SW[2][32 * 33];
    __shared__ float  PHI[1024];
    __shared__ float2 P8s[2][64];
    __shared__ float2 R8s[2][64];
    __shared__ float2 tw32[32];
    __shared__ float2 tw8[8];
    const int tid = threadIdx.x, w = tid >> 5, lane = tid & 31;
    const int pair = blockIdx.x * 2 + w;
    const int bcA = pair * 2, bcB = bcA + 1;

    if (blockIdx.x == 0 && w == 0) {
        for (int i = lane; i < 640; i += 32) out[i] = bias[i % 10];
    }

    if (tid < 32) { float s, c; sincospif((float)tid * (1.0f / 16.0f), &s, &c); tw32[tid] = make_float2(c, s); }
    else if (tid < 40) { const int j = tid - 32; float s, c; sincospif((float)j * 0.25f, &s, &c); tw8[j] = make_float2(c, s); }
    for (int i = tid; i < 1024; i += 64) PHI[i] = phi[i];
    __syncthreads();           // tw + PHI visible to both warps

    float2 v[32];
    float2* const S = SW[w];

    // packed rows fwd: lane owns row `lane` of both images
    {
        const float* xa = x + bcA * 1024 + lane * 32;
        const float* xb = x + bcB * 1024 + lane * 32;
#pragma unroll
        for (int n = 0; n < 32; n++) v[n] = make_float2(xa[n], xb[n]);
    }
    fft_serial<32, false>(v, tw32);
#pragma unroll
    for (int n = 0; n < 32; n++) S[lane * 33 + brevn(n, 5)] = v[n];
    __syncwarp();

    // packed cols fwd -> natural-order packed spectrum
#pragma unroll
    for (int m = 0; m < 32; m++) v[m] = S[m * 33 + lane];
    fft_serial<32, false>(v, tw32);
#pragma unroll
    for (int m = 0; m < 32; m++) S[brevn(m, 5) * 33 + lane] = v[m];
    __syncwarp();

    // unpack via conjugate symmetry -> g_xf for both tiles
    {
        const int lnn = (32 - lane) & 31;
        float2* dstA = g_xf + bcA * 1024;
        float2* dstB = dstA + 1024;
#pragma unroll
        for (int m = 0; m < 32; m++) {
            const float2 z1 = S[m * 33 + lane];
            const float2 z2 = S[(((32 - m) & 31)) * 33 + lnn];
            dstA[m * 32 + lane] = make_float2(0.5f * (z1.x + z2.x), 0.5f * (z1.y - z2.y));
            dstB[m * 32 + lane] = make_float2(0.5f * (z1.y + z2.y), 0.5f * (z2.x - z1.x));
        }
    }

    // s0 packed tail: p8 = sub4(Z*phi)
#pragma unroll
    for (int k = 0; k < 2; k++) {
        const int o = lane + 32 * k;
        const int u = o >> 3, vv = o & 7;
        float ar = 0.f, ai = 0.f;
#pragma unroll
        for (int i = 0; i < 4; i++)
#pragma unroll
            for (int j = 0; j < 4; j++) {
                const float p = PHI[(8 * i + u) * 32 + 8 * j + vv];
                const float2 z = S[(8 * i + u) * 33 + 8 * j + vv];
                ar = fmaf(z.x, p, ar); ai = fmaf(z.y, p, ai);
            }
        P8s[w][o] = make_float2(ar * 0.0625f, ai * 0.0625f);
    }
    __syncwarp();

    // separable complex ifft8: row pass
#pragma unroll
    for (int k = 0; k < 2; k++) {
        const int o = lane + 32 * k;
        const int y = o >> 3, vv = o & 7;
        float ar = 0.f, ai = 0.f;
#pragma unroll
        for (int u = 0; u < 8; u++) {
            const float2 p = P8s[w][u * 8 + vv];
            const float2 w8 = tw8[(y * u) & 7];
            ar = fmaf(p.x, w8.x, fmaf(-p.y, w8.y, ar));
            ai = fmaf(p.y, w8.x, fmaf( p.x, w8.y, ai));
        }
        R8s[w][o] = make_float2(ar, ai);
    }
    __syncwarp();

    // col pass: Re -> bcA channel 0, Im -> bcB channel 0
#pragma unroll
    for (int k = 0; k < 2; k++) {
        const int o = lane + 32 * k;
        const int y = o >> 3, xx = o & 7;
        float ar = 0.f, ai = 0.f;
#pragma unroll
        for (int vv = 0; vv < 8; vv++) {
            const float2 p = R8s[w][y * 8 + vv];
            const float2 w8 = tw8[(xx * vv) & 7];
            ar = fmaf(p.x, w8.x, fmaf(-p.y, w8.y, ar));
            ai = fmaf(p.y, w8.x, fmaf( p.x, w8.y, ai));
        }
        g_feat[bcA * 81 * 64 + o] = ar * (1.0f / 64.0f);
        g_feat[bcB * 81 * 64 + o] = ai * (1.0f / 64.0f);
    }
}

// ---------------- K2: u0f per (bc, t1); s1a — 3 block barriers, rest warp-local ----------------
__global__ void __launch_bounds__(T128)
k2_u0f(const float* __restrict__ psi0, const float* __restrict__ phi) {
    __shared__ float2 XF[32 * 33];
    __shared__ float2 ZW[4][32 * 33];
    __shared__ float  PHI[1024];
    __shared__ float2 P8s[2][64];
    __shared__ float2 R8s[2][64];
    __shared__ float2 tw32[32];
    __shared__ float2 tw8[8];
    const int tid = threadIdx.x;
    const int bc = blockIdx.x >> 1, half = blockIdx.x & 1;
    const int w = tid >> 5, lane = tid & 31;
    const int t1 = half * 4 + w;

    if (tid < 32) { float s, c; sincospif((float)tid * (1.0f / 16.0f), &s, &c); tw32[tid] = make_float2(c, s); }
    else if (tid < 40) { const int j = tid - 32; float s, c; sincospif((float)j * 0.25f, &s, &c); tw8[j] = make_float2(c, s); }

    const float2* xf = g_xf + bc * 1024;
    for (int i = tid; i < 1024; i += T128) {
        XF[(i >> 5) * 33 + (i & 31)] = xf[i];
        PHI[i] = phi[i];
    }
    __syncthreads();                                   // B1: XF/PHI ready

    float2 v[32];
    // inverse rows on xf * psi0[t1] -> ZW[w]
    {
        const float* ps = psi0 + t1 * 1024 + lane * 32;
#pragma unroll
        for (int n = 0; n < 32; n++) {
            const float p = ps[n];
            const float2 z = XF[lane * 33 + n];
            v[n] = make_float2(z.x * p, z.y * p);
        }
    }
    fft_serial<32, true>(v, tw32);
#pragma unroll
    for (int n = 0; n < 32; n++) ZW[w][lane * 33 + brevn(n, 5)] = v[n];
    __syncwarp();

    // inverse cols + modulus -> u in v[m].x
#pragma unroll
    for (int m = 0; m < 32; m++) v[m] = ZW[w][m * 33 + lane];
    fft_serial<32, true>(v, tw32);
#pragma unroll
    for (int m = 0; m < 32; m++)
        v[m].x = sqrtf(v[m].x * v[m].x + v[m].y * v[m].y) * (1.0f / 1024.0f);
    __syncthreads();                                   // B2

    // pack
    {
        float* dstf = (float*)ZW[w >> 1];
        const int comp = w & 1;
#pragma unroll
        for (int m = 0; m < 32; m++)
            dstf[(brevn(m, 5) * 33 + lane) * 2 + comp] = v[m].x;
    }
    __syncthreads();                                   // B3

    if (w < 2) {
        const int p = w;
        float2* const S = ZW[p];

#pragma unroll
        for (int n = 0; n < 32; n++) v[n] = S[lane * 33 + n];
        fft_serial<32, false>(v, tw32);
#pragma unroll
        for (int n = 0; n < 32; n++) S[lane * 33 + brevn(n, 5)] = v[n];
        __syncwarp();

#pragma unroll
        for (int m = 0; m < 32; m++) v[m] = S[m * 33 + lane];
        fft_serial<32, false>(v, tw32);
#pragma unroll
        for (int m = 0; m < 32; m++) S[brevn(m, 5) * 33 + lane] = v[m];
        __syncwarp();

        // unpack + store u0f
        {
            const int lnn = (32 - lane) & 31;
            float2* dstA = g_u0f + (bc * 8 + half * 4 + 2 * p) * 1024;
            float2* dstB = dstA + 1024;
#pragma unroll
            for (int m = 0; m < 32; m++) {
                const float2 z1 = S[m * 33 + lane];
                const float2 z2 = S[(((32 - m) & 31)) * 33 + lnn];
                dstA[m * 32 + lane] = make_float2(0.5f * (z1.x + z2.x), 0.5f * (z1.y - z2.y));
                dstB[m * 32 + lane] = make_float2(0.5f * (z1.y + z2.y), 0.5f * (z2.x - z1.x));
            }
        }

        // s1a packed tail
#pragma unroll
        for (int k = 0; k < 2; k++) {
            const int o = lane + 32 * k;
            const int u = o >> 3, vv = o & 7;
            float ar = 0.f, ai = 0.f;
#pragma unroll
            for (int i = 0; i < 4; i++)
#pragma unroll
                for (int j = 0; j < 4; j++) {
                    const float pphi = PHI[(8 * i + u) * 32 + 8 * j + vv];
                    const float2 z = S[(8 * i + u) * 33 + 8 * j + vv];
                    ar = fmaf(z.x, pphi, ar); ai = fmaf(z.y, pphi, ai);
                }
            P8s[p][o] = make_float2(ar * 0.0625f, ai * 0.0625f);
        }
        __syncwarp();

#pragma unroll
        for (int k = 0; k < 2; k++) {
            const int o = lane + 32 * k;
            const int y = o >> 3, vv = o & 7;
            float ar = 0.f, ai = 0.f;
#pragma unroll
            for (int u = 0; u < 8; u++) {
                const float2 pz = P8s[p][u * 8 + vv];
                const float2 w8 = tw8[(y * u) & 7];
                ar = fmaf(pz.x, w8.x, fmaf(-pz.y, w8.y, ar));
                ai = fmaf(pz.y, w8.x, fmaf( pz.x, w8.y, ai));
            }
            R8s[p][o] = make_float2(ar, ai);
        }
        __syncwarp();

#pragma unroll
        for (int k = 0; k < 2; k++) {
            const int o = lane + 32 * k;
            const int y = o >> 3, xx = o & 7;
            float ar = 0.f, ai = 0.f;
#pragma unroll
            for (int vv = 0; vv < 8; vv++) {
                const float2 pz = R8s[p][y * 8 + vv];
                const float2 w8 = tw8[(xx * vv) & 7];
                ar = fmaf(pz.x, w8.x, fmaf(-pz.y, w8.y, ar));
                ai = fmaf(pz.y, w8.x, fmaf( pz.x, w8.y, ai));
            }
            float* fb = g_feat + bc * 81 * 64 + (1 + half * 4 + 2 * p) * 64;
            fb[o]      = ar * (1.0f / 64.0f);
            fb[64 + o] = ai * (1.0f / 64.0f);
        }
    }
}

// ---------------- K3: warp-decomposed P16 pipelines (one block barrier) ----------------
__global__ void __launch_bounds__(T128, 6)
k3_p16(const float* __restrict__ psi1, const float* __restrict__ phi) {
    __shared__ float2 Q[8][16 * 17];     // per-tile spectra; Q[2w] aliased as packed UP after stage C
    __shared__ float  PHI1[256];
    __shared__ float2 P8W[4][64];
    __shared__ float2 R8W[4][64];
    __shared__ float2 tw16[16];
    __shared__ float2 tw8[8];
    const int tid = threadIdx.x;
    const int w = tid >> 5, lane = tid & 31;
    const int h = lane >> 4, ln = lane & 15;
    const int bc = blockIdx.x / 9;
    const int role = blockIdx.x - bc * 9;

    const float2* __restrict__ src = (role == 0) ? (g_xf + bc * 1024)
                                                 : (g_u0f + (bc * 8 + role - 1) * 1024);
    const int chbase = (role == 0) ? 9 : 17 + (role - 1) * 8;

    if (tid < 16) { float s, c; sincospif((float)tid * 0.125f, &s, &c); tw16[tid] = make_float2(c, s); }
    else if (tid < 24) { const int j = tid - 16; float s, c; sincospif((float)j * 0.25f, &s, &c); tw8[j] = make_float2(c, s); }

#pragma unroll
    for (int k = 0; k < 2; k++) {
        const int idx = tid + 128 * k;
        const int a = idx >> 4, b2 = idx & 15;
        PHI1[idx] = 0.25f * (phi[a * 32 + b2] + phi[(a + 16) * 32 + b2] +
                             phi[a * 32 + b2 + 16] + phi[(a + 16) * 32 + b2 + 16]);
    }

    // Stage A (block-wide, output-stationary over the 8 psi tiles)
#pragma unroll
    for (int k = 0; k < 2; k++) {
        const int e = tid + 128 * k;
        const int a = e >> 4, b2 = e & 15;
        const int o00 = a * 32 + b2;
        const float2 z00 = src[o00],       z01 = src[o00 + 16];
        const float2 z10 = src[o00 + 512], z11 = src[o00 + 528];
#pragma unroll
        for (int t = 0; t < 8; t++) {
            const float* ps = psi1 + t * 1024;
            const float p00 = ps[o00],       p01 = ps[o00 + 16];
            const float p10 = ps[o00 + 512], p11 = ps[o00 + 528];
            float ar = fmaf(z00.x, p00, fmaf(z01.x, p01, fmaf(z10.x, p10, z11.x * p11)));
            float ai = fmaf(z00.y, p00, fmaf(z01.y, p01, fmaf(z10.y, p10, z11.y * p11)));
            Q[t][a * 17 + b2] = make_float2(0.25f * ar, 0.25f * ai);
        }
    }
    __syncthreads();     // the ONLY block barrier

    float2 v[16];
    const int tb = 2 * w + h;
    float2* const QT = Q[tb];
    float2* const UPW = Q[2 * w];
    float* const upf = (float*)UPW;

    // Stage B: rows inverse
#pragma unroll
    for (int n = 0; n < 16; n++) v[n] = QT[ln * 17 + n];
    fft_serial<16, true>(v, tw16);
#pragma unroll
    for (int n = 0; n < 16; n++) QT[ln * 17 + brevn(n, 4)] = v[n];
    __syncwarp();

    // Stage C: cols inverse + modulus; packed write into UPW
#pragma unroll
    for (int m = 0; m < 16; m++) v[m] = QT[m * 17 + ln];
    __syncwarp();
    fft_serial<16, true>(v, tw16);
#pragma unroll
    for (int m = 0; m < 16; m++) {
        const float u = sqrtf(v[m].x * v[m].x + v[m].y * v[m].y) * (1.0f / 256.0f);
        upf[(brevn(m, 4) * 17 + ln) * 2 + h] = u;
    }
    __syncwarp();

    // Stage D: rows fwd on packed u (lanes 0-15)
    if (h == 0) {
#pragma unroll
        for (int n = 0; n < 16; n++) v[n] = UPW[ln * 17 + n];
        fft_serial<16, false>(v, tw16);
#pragma unroll
        for (int n = 0; n < 16; n++) UPW[ln * 17 + brevn(n, 4)] = v[n];
    }
    __syncwarp();

    // Stage E: cols fwd
    if (h == 0) {
#pragma unroll
        for (int m = 0; m < 16; m++) v[m] = UPW[m * 17 + ln];
        fft_serial<16, false>(v, tw16);
#pragma unroll
        for (int m = 0; m < 16; m++) UPW[brevn(m, 4) * 17 + ln] = v[m];
    }
    __syncwarp();

    // Stage F: p8 = sub2(Zpacked * phi1)
#pragma unroll
    for (int k = 0; k < 2; k++) {
        const int o = lane + 32 * k;
        const int u = o >> 3, vv = o & 7;
        float ar = 0.f, ai = 0.f;
#pragma unroll
        for (int i = 0; i < 2; i++)
#pragma unroll
            for (int j = 0; j < 2; j++) {
                const float p = PHI1[(8 * i + u) * 16 + 8 * j + vv];
                const float2 z = UPW[(8 * i + u) * 17 + 8 * j + vv];
                ar = fmaf(z.x, p, ar); ai = fmaf(z.y, p, ai);
            }
        P8W[w][o] = make_float2(0.25f * ar, 0.25f * ai);
    }
    __syncwarp();

    // Stage G1: separable ifft8 — row pass
#pragma unroll
    for (int k = 0; k < 2; k++) {
        const int o = lane + 32 * k;
        const int y = o >> 3, vv = o & 7;
        float ar = 0.f, ai = 0.f;
#pragma unroll
        for (int u = 0; u < 8; u++) {
            const float2 p = P8W[w][u * 8 + vv];
            const float2 w8 = tw8[(y * u) & 7];
            ar = fmaf(p.x, w8.x, fmaf(-p.y, w8.y, ar));
            ai = fmaf(p.y, w8.x, fmaf( p.x, w8.y, ai));
        }
        R8W[w][o] = make_float2(ar, ai);
    }
    __syncwarp();

    // Stage G2: col pass; Re -> chbase+2w, Im -> chbase+2w+1
    float* fb = g_feat + bc * 81 * 64;
#pragma unroll
    for (int k = 0; k < 2; k++) {
        const int o = lane + 32 * k;
        const int y = o >> 3, xx = o & 7;
        float ar = 0.f, ai = 0.f;
#pragma unroll
        for (int vv = 0; vv < 8; vv++) {
            const float2 p = R8W[w][y * 8 + vv];
            const float2 w8 = tw8[(xx * vv) & 7];
            ar = fmaf(p.x, w8.x, fmaf(-p.y, w8.y, ar));
            ai = fmaf(p.y, w8.x, fmaf( p.x, w8.y, ai));
        }
        fb[(chbase + 2 * w)     * 64 + o] = ar * (1.0f / 64.0f);
        fb[(chbase + 2 * w + 1) * 64 + o] = ai * (1.0f / 64.0f);
    }
}

// ---------------- K4: fused stats/GEMV, 512 threads (one float4 per thread) ----------------
__global__ void __launch_bounds__(512)
k4_gemv(const float* __restrict__ gamma, const float* __restrict__ beta,
        const float* __restrict__ W, float* __restrict__ out) {
    const int b = blockIdx.x / 9, c = blockIdx.x - (blockIdx.x / 9) * 9;
    const float* f = g_feat + b * 15552 + c * 1728;   // 3 complete groups of 576
    __shared__ float smu[3], srs[3];
    __shared__ float redA[3][2], redB[3][2];
    __shared__ float sA[27], sB[27];
    const int tid = threadIdx.x;

    if (tid < 192) {
        const int g = tid >> 6, l = tid & 63;
        const float4* fg4 = (const float4*)(f + g * 576);   // 144 float4 per group
        float s = 0.f, s2 = 0.f;
#pragma unroll
        for (int it = 0; it < 3; it++) {
            const int i4 = l + 64 * it;
            if (i4 < 144) {
                const float4 xv = fg4[i4];
                s += xv.x + xv.y + xv.z + xv.w;
                s2 = fmaf(xv.x, xv.x, fmaf(xv.y, xv.y, fmaf(xv.z, xv.z, fmaf(xv.w, xv.w, s2))));
            }
        }
#pragma unroll
        for (int o = 16; o > 0; o >>= 1) {
            s  += __shfl_xor_sync(0xffffffffu, s,  o);
            s2 += __shfl_xor_sync(0xffffffffu, s2, o);
        }
        if ((l & 31) == 0) { redA[g][l >> 5] = s; redB[g][l >> 5] = s2; }
    }
    __syncthreads();
    if (tid < 3) {
        const float s = redA[tid][0] + redA[tid][1];
        const float s2 = redB[tid][0] + redB[tid][1];
        const float m = s * (1.0f / 576.0f);
        smu[tid] = m;
        srs[tid] = rsqrtf(s2 * (1.0f / 576.0f) - m * m + 1e-5f);
    }
    __syncthreads();
    if (tid < 27) {
        const int gl = tid / 9;
        const int ch = c * 27 + tid;
        const float a = srs[gl] * gamma[ch];
        sA[tid] = a;
        sB[tid] = beta[ch] - smu[gl] * a;
    }
    __syncthreads();

    // GEMV: 432 float4, one per thread (tid < 432)
    float acc[10];
#pragma unroll
    for (int j = 0; j < 10; j++) acc[j] = 0.f;
    const float4* __restrict__ f4 = (const float4*)f;
    const float4* __restrict__ W4 = (const float4*)(W + c * 1728);
    if (tid < 432) {
        const int ch = tid >> 4;
        const float a = sA[ch], bb = sB[ch];
        const float4 fv = f4[tid];
        float4 nv;
        nv.x = fmaf(fv.x, a, bb);
        nv.y = fmaf(fv.y, a, bb);
        nv.z = fmaf(fv.z, a, bb);
        nv.w = fmaf(fv.w, a, bb);
#pragma unroll
        for (int j = 0; j < 10; j++) {
            const float4 wv = W4[j * 3888 + tid];
            acc[j] = fmaf(nv.x, wv.x,
                     fmaf(nv.y, wv.y,
                     fmaf(nv.z, wv.z,
                     fmaf(nv.w, wv.w, acc[j]))));
        }
    }

    __shared__ float red[16][10];
    const int lane = tid & 31, wrp = tid >> 5;
#pragma unroll
    for (int j = 0; j < 10; j++) {
        float vv = acc[j];
#pragma unroll
        for (int o = 16; o > 0; o >>= 1) vv += __shfl_xor_sync(0xffffffffu, vv, o);
        if (lane == 0) red[wrp][j] = vv;
    }
    __syncthreads();
    if (tid < 10) {
        float vv = 0.f;
#pragma unroll
        for (int w = 0; w < 14; w++) vv += red[w][tid];   // warps 14,15 are all-zero (tid>=448)
        atomicAdd(&out[b * 10 + tid], vv);
    }
}

// ---------------- launch ----------------
extern "C" void kernel_launch(void* const* d_in, const int* in_sizes, int n_in,
                              void* d_out, int out_size) {
    const float* x     = (const float*)d_in[0];
    const float* psi0  = (const float*)d_in[1];
    const float* psi1  = (const float*)d_in[2];
    const float* phi   = (const float*)d_in[3];
    const float* gamma = (const float*)d_in[4];
    const float* beta  = (const float*)d_in[5];
    const float* W     = (const float*)d_in[6];
    const float* bias  = (const float*)d_in[7];
    float* out = (float*)d_out;

    k1_xf  <<<48,       64  >>>(x, phi, bias, out);
    k2_u0f <<<384,      T128>>>(psi0, phi);
    k3_p16 <<<192 * 9,  T128>>>(psi1, phi);
    k4_gemv<<<64 * 9,   512 >>>(gamma, beta, W, out);
}

// round 12
// speedup vs baseline: 1.1205x; 1.1205x over previous
#include <cuda_runtime.h>
#include <math.h>

#define T256 256
#define T128 128

// ---------------- global scratch (static, no allocation) ----------------
static __device__ float  g_feat[64 * 243 * 64];   // (b*3+c)*81*64 + ch*64 + pix
static __device__ float2 g_xf  [192 * 1024];      // fft2(x) per (b,c)
static __device__ float2 g_u0f [1536 * 1024];     // fft2(|ifft2(xf*psi0)|) per (bc,t1)

__device__ __forceinline__ int brevn(int i, int bits) {
    return (int)(__brev((unsigned)i) >> (32 - bits));
}

// ---------------- serial register-resident radix-2 DIF FFT ----------------
template<int N, bool INV>
__device__ __forceinline__ void fft_serial(float2* v, const float2* __restrict__ tw) {
#pragma unroll
    for (int m = N; m >= 2; m >>= 1) {
        const int half = m >> 1, step = N / m;
#pragma unroll
        for (int k0 = 0; k0 < N; k0 += m) {
#pragma unroll
            for (int j = 0; j < half; j++) {
                const int lo = k0 + j, hi = lo + half;
                const float2 a = v[lo], b = v[hi];
                const float2 d = make_float2(a.x - b.x, a.y - b.y);
                v[lo] = make_float2(a.x + b.x, a.y + b.y);
                if (j == 0) {
                    v[hi] = d;
                } else if (j * step == N / 4) {
                    v[hi] = INV ? make_float2(-d.y, d.x) : make_float2(d.y, -d.x);
                } else {
                    const float2 w = tw[j * step];
                    const float ws = INV ? w.y : -w.y;
                    v[hi] = make_float2(d.x * w.x - d.y * ws, d.y * w.x + d.x * ws);
                }
            }
        }
    }
}

// ---------------- k1 helpers (register-blocked direct DFT) ----------------
__device__ __forceinline__ void fwd_rows_real32(const float* __restrict__ in, float2* __restrict__ out,
                                                const float2* __restrict__ tw) {
    const int lane = threadIdx.x & 31, warp = threadIdx.x >> 5;
    float ar[4] = {0,0,0,0}, ai[4] = {0,0,0,0};
#pragma unroll
    for (int n = 0; n < 32; n++) {
        const float2 w = tw[(lane * n) & 31];
#pragma unroll
        for (int i = 0; i < 4; i++) {
            const float v = in[(warp + 8 * i) * 32 + n];
            ar[i] = fmaf(v,  w.x, ar[i]);
            ai[i] = fmaf(v, -w.y, ai[i]);
        }
    }
#pragma unroll
    for (int i = 0; i < 4; i++) out[(warp + 8 * i) * 32 + lane] = make_float2(ar[i], ai[i]);
}

__device__ __forceinline__ void fwd_cols32(const float2* __restrict__ in, float2* __restrict__ out,
                                           const float2* __restrict__ tw) {
    const int lane = threadIdx.x & 31, warp = threadIdx.x >> 5;
    float ar[4] = {0,0,0,0}, ai[4] = {0,0,0,0};
#pragma unroll
    for (int m = 0; m < 32; m++) {
        const float2 v = in[m * 32 + lane];
#pragma unroll
        for (int i = 0; i < 4; i++) {
            const float2 w = tw[((warp + 8 * i) * m) & 31];
            ar[i] = fmaf(v.x, w.x, fmaf( v.y, w.y, ar[i]));
            ai[i] = fmaf(v.y, w.x, fmaf(-v.x, w.y, ai[i]));
        }
    }
#pragma unroll
    for (int i = 0; i < 4; i++) out[(warp + 8 * i) * 32 + lane] = make_float2(ar[i], ai[i]);
}

__device__ __forceinline__ void p8_from32(const float2* __restrict__ S, const float* __restrict__ PHI,
                                          float2* __restrict__ P8) {
    const int tid = threadIdx.x;
    if (tid < 64) {
        const int u = tid >> 3, v = tid & 7;
        float ar = 0.f, ai = 0.f;
#pragma unroll
        for (int i = 0; i < 4; i++)
#pragma unroll
            for (int j = 0; j < 4; j++) {
                const int off = (8 * i + u) * 32 + 8 * j + v;
                const float p = PHI[off];
                const float2 z = S[off];
                ar = fmaf(z.x, p, ar); ai = fmaf(z.y, p, ai);
            }
        P8[tid] = make_float2(ar * 0.0625f, ai * 0.0625f);
    }
}

__device__ __forceinline__ void ifft8_store64(const float2* __restrict__ P8, const float2* __restrict__ tw8,
                                              float* __restrict__ dst) {
    const int tid = threadIdx.x;
    if (tid < 64) {
        const int y = tid >> 3, xx = tid & 7;
        float acc = 0.f;
#pragma unroll
        for (int u = 0; u < 8; u++)
#pragma unroll
            for (int v = 0; v < 8; v++) {
                const int ph = (y * u + xx * v) & 7;
                const float2 p = P8[u * 8 + v];
                const float2 w = tw8[ph];
                acc = fmaf(p.x, w.x, fmaf(-p.y, w.y, acc));
            }
        dst[tid] = acc * (1.0f / 64.0f);
    }
}

// ---------------- K1: xf = fft2(x); s0; out init (block 0) ----------------
__global__ void __launch_bounds__(T256)
k1_xf(const float* __restrict__ x, const float* __restrict__ phi,
      const float* __restrict__ bias, float* __restrict__ out) {
    __shared__ float  U[1024];
    __shared__ float2 Z[1024];
    __shared__ float2 XF[1024];
    __shared__ float  PHI[1024];
    __shared__ float2 P8[64];
    __shared__ float2 tw32[32];
    __shared__ float2 tw8[8];
    const int tid = threadIdx.x, bc = blockIdx.x;

    if (bc == 0) {
        for (int i = tid; i < 640; i += T256) out[i] = bias[i % 10];
    }

    if (tid < 32) { float s, c; sincospif((float)tid * (1.0f / 16.0f), &s, &c); tw32[tid] = make_float2(c, s); }
    else if (tid < 40) { const int j = tid - 32; float s, c; sincospif((float)j * 0.25f, &s, &c); tw8[j] = make_float2(c, s); }
    for (int i = tid; i < 1024; i += T256) { U[i] = x[bc * 1024 + i]; PHI[i] = phi[i]; }
    __syncthreads();

    fwd_rows_real32(U, Z, tw32);
    __syncthreads();
    fwd_cols32(Z, XF, tw32);
    __syncthreads();

    float2* dst = g_xf + bc * 1024;
    for (int i = tid; i < 1024; i += T256) dst[i] = XF[i];

    p8_from32(XF, PHI, P8);
    __syncthreads();
    ifft8_store64(P8, tw8, g_feat + bc * 81 * 64);
}

// ---------------- K2: u0f per (bc, t1); s1a — forward-packed pairs (round-10 proven) ----------------
__global__ void __launch_bounds__(T128)
k2_u0f(const float* __restrict__ psi0, const float* __restrict__ phi) {
    __shared__ float2 XF[32 * 33];
    __shared__ float2 ZW[4][32 * 33];
    __shared__ float  PHI[1024];
    __shared__ float2 P8s[2][64];
    __shared__ float2 R8s[2][64];
    __shared__ float2 tw32[32];
    __shared__ float2 tw8[8];
    const int tid = threadIdx.x;
    const int bc = blockIdx.x >> 1, half = blockIdx.x & 1;
    const int w = tid >> 5, lane = tid & 31;
    const int t1 = half * 4 + w;

    if (tid < 32) { float s, c; sincospif((float)tid * (1.0f / 16.0f), &s, &c); tw32[tid] = make_float2(c, s); }
    else if (tid < 40) { const int j = tid - 32; float s, c; sincospif((float)j * 0.25f, &s, &c); tw8[j] = make_float2(c, s); }

    const float2* xf = g_xf + bc * 1024;
    for (int i = tid; i < 1024; i += T128) {
        XF[(i >> 5) * 33 + (i & 31)] = xf[i];
        PHI[i] = phi[i];
    }
    __syncthreads();                                   // B1: XF/PHI ready

    float2 v[32];
    // inverse rows on xf * psi0[t1] -> ZW[w]
    {
        const float* ps = psi0 + t1 * 1024 + lane * 32;
#pragma unroll
        for (int n = 0; n < 32; n++) {
            const float p = ps[n];
            const float2 z = XF[lane * 33 + n];
            v[n] = make_float2(z.x * p, z.y * p);
        }
    }
    fft_serial<32, true>(v, tw32);
#pragma unroll
    for (int n = 0; n < 32; n++) ZW[w][lane * 33 + brevn(n, 5)] = v[n];
    __syncwarp();

    // inverse cols + modulus -> u in v[m].x
#pragma unroll
    for (int m = 0; m < 32; m++) v[m] = ZW[w][m * 33 + lane];
    fft_serial<32, true>(v, tw32);
#pragma unroll
    for (int m = 0; m < 32; m++)
        v[m].x = sqrtf(v[m].x * v[m].x + v[m].y * v[m].y) * (1.0f / 1024.0f);
    __syncthreads();                                   // B2

    // pack: pair p = w>>1 buffer, component = w&1
    {
        float* dstf = (float*)ZW[w >> 1];
        const int comp = w & 1;
#pragma unroll
        for (int m = 0; m < 32; m++)
            dstf[(brevn(m, 5) * 33 + lane) * 2 + comp] = v[m].x;
    }
    __syncthreads();                                   // B3

    if (w < 2) {
        const int p = w;
        float2* const S = ZW[p];

#pragma unroll
        for (int n = 0; n < 32; n++) v[n] = S[lane * 33 + n];
        fft_serial<32, false>(v, tw32);
#pragma unroll
        for (int n = 0; n < 32; n++) S[lane * 33 + brevn(n, 5)] = v[n];
        __syncwarp();

#pragma unroll
        for (int m = 0; m < 32; m++) v[m] = S[m * 33 + lane];
        fft_serial<32, false>(v, tw32);
#pragma unroll
        for (int m = 0; m < 32; m++) S[brevn(m, 5) * 33 + lane] = v[m];
        __syncwarp();

        // unpack via conjugate symmetry, store both u0f spectra
        {
            const int lnn = (32 - lane) & 31;
            float2* dstA = g_u0f + (bc * 8 + half * 4 + 2 * p) * 1024;
            float2* dstB = dstA + 1024;
#pragma unroll
            for (int m = 0; m < 32; m++) {
                const float2 z1 = S[m * 33 + lane];
                const float2 z2 = S[(((32 - m) & 31)) * 33 + lnn];
                dstA[m * 32 + lane] = make_float2(0.5f * (z1.x + z2.x), 0.5f * (z1.y - z2.y));
                dstB[m * 32 + lane] = make_float2(0.5f * (z1.y + z2.y), 0.5f * (z2.x - z1.x));
            }
        }

        // s1a packed tail: p8 = sub4(Z*phi)
#pragma unroll
        for (int k = 0; k < 2; k++) {
            const int o = lane + 32 * k;
            const int u = o >> 3, vv = o & 7;
            float ar = 0.f, ai = 0.f;
#pragma unroll
            for (int i = 0; i < 4; i++)
#pragma unroll
                for (int j = 0; j < 4; j++) {
                    const float pphi = PHI[(8 * i + u) * 32 + 8 * j + vv];
                    const float2 z = S[(8 * i + u) * 33 + 8 * j + vv];
                    ar = fmaf(z.x, pphi, ar); ai = fmaf(z.y, pphi, ai);
                }
            P8s[p][o] = make_float2(ar * 0.0625f, ai * 0.0625f);
        }
        __syncwarp();

        // separable complex ifft8: row pass
#pragma unroll
        for (int k = 0; k < 2; k++) {
            const int o = lane + 32 * k;
            const int y = o >> 3, vv = o & 7;
            float ar = 0.f, ai = 0.f;
#pragma unroll
            for (int u = 0; u < 8; u++) {
                const float2 pz = P8s[p][u * 8 + vv];
                const float2 w8 = tw8[(y * u) & 7];
                ar = fmaf(pz.x, w8.x, fmaf(-pz.y, w8.y, ar));
                ai = fmaf(pz.y, w8.x, fmaf( pz.x, w8.y, ai));
            }
            R8s[p][o] = make_float2(ar, ai);
        }
        __syncwarp();

        // col pass: Re -> even tile, Im -> odd tile
#pragma unroll
        for (int k = 0; k < 2; k++) {
            const int o = lane + 32 * k;
            const int y = o >> 3, xx = o & 7;
            float ar = 0.f, ai = 0.f;
#pragma unroll
            for (int vv = 0; vv < 8; vv++) {
                const float2 pz = R8s[p][y * 8 + vv];
                const float2 w8 = tw8[(xx * vv) & 7];
                ar = fmaf(pz.x, w8.x, fmaf(-pz.y, w8.y, ar));
                ai = fmaf(pz.y, w8.x, fmaf( pz.x, w8.y, ai));
            }
            float* fb = g_feat + bc * 81 * 64 + (1 + half * 4 + 2 * p) * 64;
            fb[o]      = ar * (1.0f / 64.0f);
            fb[64 + o] = ai * (1.0f / 64.0f);
        }
    }
}

// ---------------- K3: warp-decomposed P16 pipelines; try 7 CTAs/SM ----------------
__global__ void __launch_bounds__(T128, 7)
k3_p16(const float* __restrict__ psi1, const float* __restrict__ phi) {
    __shared__ float2 Q[8][16 * 17];     // per-tile spectra; Q[2w] aliased as packed UP after stage C
    __shared__ float  PHI1[256];
    __shared__ float2 P8W[4][64];
    __shared__ float2 R8W[4][64];
    __shared__ float2 tw16[16];
    __shared__ float2 tw8[8];
    const int tid = threadIdx.x;
    const int w = tid >> 5, lane = tid & 31;
    const int h = lane >> 4, ln = lane & 15;
    const int bc = blockIdx.x / 9;
    const int role = blockIdx.x - bc * 9;

    const float2* __restrict__ src = (role == 0) ? (g_xf + bc * 1024)
                                                 : (g_u0f + (bc * 8 + role - 1) * 1024);
    const int chbase = (role == 0) ? 9 : 17 + (role - 1) * 8;

    if (tid < 16) { float s, c; sincospif((float)tid * 0.125f, &s, &c); tw16[tid] = make_float2(c, s); }
    else if (tid < 24) { const int j = tid - 16; float s, c; sincospif((float)j * 0.25f, &s, &c); tw8[j] = make_float2(c, s); }

#pragma unroll
    for (int k = 0; k < 2; k++) {
        const int idx = tid + 128 * k;
        const int a = idx >> 4, b2 = idx & 15;
        PHI1[idx] = 0.25f * (phi[a * 32 + b2] + phi[(a + 16) * 32 + b2] +
                             phi[a * 32 + b2 + 16] + phi[(a + 16) * 32 + b2 + 16]);
    }

    // Stage A (block-wide, output-stationary over the 8 psi tiles)
#pragma unroll
    for (int k = 0; k < 2; k++) {
        const int e = tid + 128 * k;
        const int a = e >> 4, b2 = e & 15;
        const int o00 = a * 32 + b2;
        const float2 z00 = src[o00],       z01 = src[o00 + 16];
        const float2 z10 = src[o00 + 512], z11 = src[o00 + 528];
#pragma unroll
        for (int t = 0; t < 8; t++) {
            const float* ps = psi1 + t * 1024;
            const float p00 = ps[o00],       p01 = ps[o00 + 16];
            const float p10 = ps[o00 + 512], p11 = ps[o00 + 528];
            float ar = fmaf(z00.x, p00, fmaf(z01.x, p01, fmaf(z10.x, p10, z11.x * p11)));
            float ai = fmaf(z00.y, p00, fmaf(z01.y, p01, fmaf(z10.y, p10, z11.y * p11)));
            Q[t][a * 17 + b2] = make_float2(0.25f * ar, 0.25f * ai);
        }
    }
    __syncthreads();     // the ONLY block barrier

    float2 v[16];
    const int tb = 2 * w + h;
    float2* const QT = Q[tb];
    float2* const UPW = Q[2 * w];
    float* const upf = (float*)UPW;

    // Stage B: rows inverse
#pragma unroll
    for (int n = 0; n < 16; n++) v[n] = QT[ln * 17 + n];
    fft_serial<16, true>(v, tw16);
#pragma unroll
    for (int n = 0; n < 16; n++) QT[ln * 17 + brevn(n, 4)] = v[n];
    __syncwarp();

    // Stage C: cols inverse + modulus; packed write into UPW
#pragma unroll
    for (int m = 0; m < 16; m++) v[m] = QT[m * 17 + ln];
    __syncwarp();
    fft_serial<16, true>(v, tw16);
#pragma unroll
    for (int m = 0; m < 16; m++) {
        const float u = sqrtf(v[m].x * v[m].x + v[m].y * v[m].y) * (1.0f / 256.0f);
        upf[(brevn(m, 4) * 17 + ln) * 2 + h] = u;
    }
    __syncwarp();

    // Stage D: rows fwd on packed u (lanes 0-15)
    if (h == 0) {
#pragma unroll
        for (int n = 0; n < 16; n++) v[n] = UPW[ln * 17 + n];
        fft_serial<16, false>(v, tw16);
#pragma unroll
        for (int n = 0; n < 16; n++) UPW[ln * 17 + brevn(n, 4)] = v[n];
    }
    __syncwarp();

    // Stage E: cols fwd
    if (h == 0) {
#pragma unroll
        for (int m = 0; m < 16; m++) v[m] = UPW[m * 17 + ln];
        fft_serial<16, false>(v, tw16);
#pragma unroll
        for (int m = 0; m < 16; m++) UPW[brevn(m, 4) * 17 + ln] = v[m];
    }
    __syncwarp();

    // Stage F: p8 = sub2(Zpacked * phi1)
#pragma unroll
    for (int k = 0; k < 2; k++) {
        const int o = lane + 32 * k;
        const int u = o >> 3, vv = o & 7;
        float ar = 0.f, ai = 0.f;
#pragma unroll
        for (int i = 0; i < 2; i++)
#pragma unroll
            for (int j = 0; j < 2; j++) {
                const float p = PHI1[(8 * i + u) * 16 + 8 * j + vv];
                const float2 z = UPW[(8 * i + u) * 17 + 8 * j + vv];
                ar = fmaf(z.x, p, ar); ai = fmaf(z.y, p, ai);
            }
        P8W[w][o] = make_float2(0.25f * ar, 0.25f * ai);
    }
    __syncwarp();

    // Stage G1: separable ifft8 — row pass
#pragma unroll
    for (int k = 0; k < 2; k++) {
        const int o = lane + 32 * k;
        const int y = o >> 3, vv = o & 7;
        float ar = 0.f, ai = 0.f;
#pragma unroll
        for (int u = 0; u < 8; u++) {
            const float2 p = P8W[w][u * 8 + vv];
            const float2 w8 = tw8[(y * u) & 7];
            ar = fmaf(p.x, w8.x, fmaf(-p.y, w8.y, ar));
            ai = fmaf(p.y, w8.x, fmaf( p.x, w8.y, ai));
        }
        R8W[w][o] = make_float2(ar, ai);
    }
    __syncwarp();

    // Stage G2: col pass; Re -> chbase+2w, Im -> chbase+2w+1
    float* fb = g_feat + bc * 81 * 64;
#pragma unroll
    for (int k = 0; k < 2; k++) {
        const int o = lane + 32 * k;
        const int y = o >> 3, xx = o & 7;
        float ar = 0.f, ai = 0.f;
#pragma unroll
        for (int vv = 0; vv < 8; vv++) {
            const float2 p = R8W[w][y * 8 + vv];
            const float2 w8 = tw8[(xx * vv) & 7];
            ar = fmaf(p.x, w8.x, fmaf(-p.y, w8.y, ar));
            ai = fmaf(p.y, w8.x, fmaf( p.x, w8.y, ai));
        }
        fb[(chbase + 2 * w)     * 64 + o] = ar * (1.0f / 64.0f);
        fb[(chbase + 2 * w + 1) * 64 + o] = ai * (1.0f / 64.0f);
    }
}

// ---------------- K4: fused stats/GEMV, float4-vectorized (round-10 proven) ----------------
__global__ void __launch_bounds__(T256)
k4_gemv(const float* __restrict__ gamma, const float* __restrict__ beta,
        const float* __restrict__ W, float* __restrict__ out) {
    const int b = blockIdx.x / 9, c = blockIdx.x - (blockIdx.x / 9) * 9;
    const float* f = g_feat + b * 15552 + c * 1728;   // 3 complete groups of 576
    __shared__ float smu[3], srs[3];
    __shared__ float redA[3][2], redB[3][2];
    __shared__ float sA[27], sB[27];
    const int tid = threadIdx.x;

    if (tid < 192) {
        const int g = tid >> 6, l = tid & 63;
        const float4* fg4 = (const float4*)(f + g * 576);   // 144 float4 per group
        float s = 0.f, s2 = 0.f;
#pragma unroll
        for (int it = 0; it < 3; it++) {
            const int i4 = l + 64 * it;
            if (i4 < 144) {
                const float4 xv = fg4[i4];
                s += xv.x + xv.y + xv.z + xv.w;
                s2 = fmaf(xv.x, xv.x, fmaf(xv.y, xv.y, fmaf(xv.z, xv.z, fmaf(xv.w, xv.w, s2))));
            }
        }
#pragma unroll
        for (int o = 16; o > 0; o >>= 1) {
            s  += __shfl_xor_sync(0xffffffffu, s,  o);
            s2 += __shfl_xor_sync(0xffffffffu, s2, o);
        }
        if ((l & 31) == 0) { redA[g][l >> 5] = s; redB[g][l >> 5] = s2; }
    }
    __syncthreads();
    if (tid < 3) {
        const float s = redA[tid][0] + redA[tid][1];
        const float s2 = redB[tid][0] + redB[tid][1];
        const float m = s * (1.0f / 576.0f);
        smu[tid] = m;
        srs[tid] = rsqrtf(s2 * (1.0f / 576.0f) - m * m + 1e-5f);
    }
    __syncthreads();
    if (tid < 27) {
        const int gl = tid / 9;
        const int ch = c * 27 + tid;
        const float a = srs[gl] * gamma[ch];
        sA[tid] = a;
        sB[tid] = beta[ch] - smu[gl] * a;
    }
    __syncthreads();

    // vectorized GEMV: 1728 floats = 432 float4; 16 float4 per channel
    float acc[10];
#pragma unroll
    for (int j = 0; j < 10; j++) acc[j] = 0.f;
    const float4* __restrict__ f4 = (const float4*)f;
    const float4* __restrict__ W4 = (const float4*)(W + c * 1728);
#pragma unroll
    for (int it = 0; it < 2; it++) {
        const int i4 = tid + T256 * it;
        if (i4 < 432) {
            const int ch = i4 >> 4;
            const float a = sA[ch], bb = sB[ch];
            const float4 fv = f4[i4];
            float4 nv;
            nv.x = fmaf(fv.x, a, bb);
            nv.y = fmaf(fv.y, a, bb);
            nv.z = fmaf(fv.z, a, bb);
            nv.w = fmaf(fv.w, a, bb);
#pragma unroll
            for (int j = 0; j < 10; j++) {
                const float4 wv = W4[j * 3888 + i4];
                acc[j] = fmaf(nv.x, wv.x,
                         fmaf(nv.y, wv.y,
                         fmaf(nv.z, wv.z,
                         fmaf(nv.w, wv.w, acc[j]))));
            }
        }
    }

    __shared__ float red[8][10];
    const int lane = tid & 31, wrp = tid >> 5;
#pragma unroll
    for (int j = 0; j < 10; j++) {
        float vv = acc[j];
#pragma unroll
        for (int o = 16; o > 0; o >>= 1) vv += __shfl_xor_sync(0xffffffffu, vv, o);
        if (lane == 0) red[wrp][j] = vv;
    }
    __syncthreads();
    if (tid < 10) {
        float vv = 0.f;
#pragma unroll
        for (int w = 0; w < 8; w++) vv += red[w][tid];
        atomicAdd(&out[b * 10 + tid], vv);
    }
}

// ---------------- launch ----------------
extern "C" void kernel_launch(void* const* d_in, const int* in_sizes, int n_in,
                              void* d_out, int out_size) {
    const float* x     = (const float*)d_in[0];
    const float* psi0  = (const float*)d_in[1];
    const float* psi1  = (const float*)d_in[2];
    const float* phi   = (const float*)d_in[3];
    const float* gamma = (const float*)d_in[4];
    const float* beta  = (const float*)d_in[5];
    const float* W     = (const float*)d_in[6];
    const float* bias  = (const float*)d_in[7];
    float* out = (float*)d_out;

    k1_xf  <<<192,      T256>>>(x, phi, bias, out);
    k2_u0f <<<384,      T128>>>(psi0, phi);
    k3_p16 <<<192 * 9,  T128>>>(psi1, phi);
    k4_gemv<<<64 * 9,   T256>>>(gamma, beta, W, out);
}

// round 13
// speedup vs baseline: 1.2252x; 1.0935x over previous
#include <cuda_runtime.h>
#include <math.h>

#define T256 256
#define T128 128

// ---------------- global scratch (static, no allocation) ----------------
static __device__ float  g_feat[64 * 243 * 64];   // (b*3+c)*81*64 + ch*64 + pix
static __device__ float2 g_xf  [192 * 1024];      // fft2(x) per (b,c) (for k3 role 0)
static __device__ float2 g_u0f [1536 * 1024];     // fft2(|ifft2(xf*psi0)|) per (bc,t1)

__device__ __forceinline__ int brevn(int i, int bits) {
    return (int)(__brev((unsigned)i) >> (32 - bits));
}

// ---------------- serial register-resident radix-2 DIF FFT ----------------
template<int N, bool INV>
__device__ __forceinline__ void fft_serial(float2* v, const float2* __restrict__ tw) {
#pragma unroll
    for (int m = N; m >= 2; m >>= 1) {
        const int half = m >> 1, step = N / m;
#pragma unroll
        for (int k0 = 0; k0 < N; k0 += m) {
#pragma unroll
            for (int j = 0; j < half; j++) {
                const int lo = k0 + j, hi = lo + half;
                const float2 a = v[lo], b = v[hi];
                const float2 d = make_float2(a.x - b.x, a.y - b.y);
                v[lo] = make_float2(a.x + b.x, a.y + b.y);
                if (j == 0) {
                    v[hi] = d;
                } else if (j * step == N / 4) {
                    v[hi] = INV ? make_float2(-d.y, d.x) : make_float2(d.y, -d.x);
                } else {
                    const float2 w = tw[j * step];
                    const float ws = INV ? w.y : -w.y;
                    v[hi] = make_float2(d.x * w.x - d.y * ws, d.y * w.x + d.x * ws);
                }
            }
        }
    }
}

// ---------------- K2 (now also does K1's job): xf, s0, u0f, s1a ----------------
// grid = 384 (bc, half), block = 128 (4 warps).
// Prologue: x staged in ZW[3]; warp 0 computes xf = fft2(x) into XF (2 serial passes).
// half==0 blocks: write g_xf, compute s0; block 0 inits out with bias.
// Then the proven round-10 k2 body: per-warp inverse, pack pairs, packed forward,
// conjugate-symmetry unpack to g_u0f, packed s1a tail.
__global__ void __launch_bounds__(T128)
k2_u0f(const float* __restrict__ x, const float* __restrict__ psi0,
       const float* __restrict__ phi, const float* __restrict__ bias,
       float* __restrict__ out) {
    __shared__ float2 XF[32 * 33];
    __shared__ float2 ZW[4][32 * 33];
    __shared__ float  PHI[1024];
    __shared__ float2 P8s[2][64];
    __shared__ float2 R8s[2][64];
    __shared__ float2 tw32[32];
    __shared__ float2 tw8[8];
    const int tid = threadIdx.x;
    const int bc = blockIdx.x >> 1, half = blockIdx.x & 1;
    const int w = tid >> 5, lane = tid & 31;
    const int t1 = half * 4 + w;

    if (blockIdx.x == 0) {
        for (int i = tid; i < 640; i += T128) out[i] = bias[i % 10];
    }

    if (tid < 32) { float s, c; sincospif((float)tid * (1.0f / 16.0f), &s, &c); tw32[tid] = make_float2(c, s); }
    else if (tid < 40) { const int j = tid - 32; float s, c; sincospif((float)j * 0.25f, &s, &c); tw8[j] = make_float2(c, s); }

    // stage x (real) in ZW[3] (dead until the inverse phase), load PHI
    {
        float* xs = (float*)ZW[3];
        const float* xin = x + bc * 1024;
        for (int i = tid; i < 1024; i += T128) {
            xs[i] = xin[i];
            PHI[i] = phi[i];
        }
    }
    __syncthreads();                                   // B0: staging + tw ready

    float2 v[32];

    // ---- prologue: warp 0 computes xf = fft2(x) into XF ----
    if (w == 0) {
        const float* xs = (const float*)ZW[3];
#pragma unroll
        for (int n = 0; n < 32; n++) v[n] = make_float2(xs[lane * 32 + n], 0.f);
        fft_serial<32, false>(v, tw32);
#pragma unroll
        for (int n = 0; n < 32; n++) XF[lane * 33 + brevn(n, 5)] = v[n];
        __syncwarp();
#pragma unroll
        for (int m = 0; m < 32; m++) v[m] = XF[m * 33 + lane];
        fft_serial<32, false>(v, tw32);
#pragma unroll
        for (int m = 0; m < 32; m++) XF[brevn(m, 5) * 33 + lane] = v[m];
    }
    __syncthreads();                                   // B1: XF ready for all warps

    // ---- half-0 extras: g_xf store + s0 ----
    if (half == 0) {
        float2* dst = g_xf + bc * 1024;
        for (int i = tid; i < 1024; i += T128)
            dst[i] = XF[(i >> 5) * 33 + (i & 31)];

        if (tid < 64) {
            const int u = tid >> 3, vv = tid & 7;
            float ar = 0.f, ai = 0.f;
#pragma unroll
            for (int i = 0; i < 4; i++)
#pragma unroll
                for (int j = 0; j < 4; j++) {
                    const float p = PHI[(8 * i + u) * 32 + 8 * j + vv];
                    const float2 z = XF[(8 * i + u) * 33 + 8 * j + vv];
                    ar = fmaf(z.x, p, ar); ai = fmaf(z.y, p, ai);
                }
            P8s[0][tid] = make_float2(ar * 0.0625f, ai * 0.0625f);
        }
        __syncthreads();
        if (tid < 64) {
            const int y = tid >> 3, xx = tid & 7;
            float acc = 0.f;
#pragma unroll
            for (int u = 0; u < 8; u++)
#pragma unroll
                for (int vv = 0; vv < 8; vv++) {
                    const int ph = (y * u + xx * vv) & 7;
                    const float2 p = P8s[0][u * 8 + vv];
                    const float2 w8 = tw8[ph];
                    acc = fmaf(p.x, w8.x, fmaf(-p.y, w8.y, acc));
                }
            g_feat[bc * 81 * 64 + tid] = acc * (1.0f / 64.0f);
        }
        __syncthreads();   // P8s[0] reads done before s1a tail reuses it
    }

    // ---- inverse rows on xf * psi0[t1] -> ZW[w] ----
    {
        const float* ps = psi0 + t1 * 1024 + lane * 32;
#pragma unroll
        for (int n = 0; n < 32; n++) {
            const float p = ps[n];
            const float2 z = XF[lane * 33 + n];
            v[n] = make_float2(z.x * p, z.y * p);
        }
    }
    fft_serial<32, true>(v, tw32);
#pragma unroll
    for (int n = 0; n < 32; n++) ZW[w][lane * 33 + brevn(n, 5)] = v[n];
    __syncwarp();

    // inverse cols + modulus -> u in v[m].x
#pragma unroll
    for (int m = 0; m < 32; m++) v[m] = ZW[w][m * 33 + lane];
    fft_serial<32, true>(v, tw32);
#pragma unroll
    for (int m = 0; m < 32; m++)
        v[m].x = sqrtf(v[m].x * v[m].x + v[m].y * v[m].y) * (1.0f / 1024.0f);
    __syncthreads();                                   // B2: inverse reads done

    // pack: pair p = w>>1 buffer, component = w&1
    {
        float* dstf = (float*)ZW[w >> 1];
        const int comp = w & 1;
#pragma unroll
        for (int m = 0; m < 32; m++)
            dstf[(brevn(m, 5) * 33 + lane) * 2 + comp] = v[m].x;
    }
    __syncthreads();                                   // B3: pack complete

    if (w < 2) {
        const int p = w;
        float2* const S = ZW[p];

#pragma unroll
        for (int n = 0; n < 32; n++) v[n] = S[lane * 33 + n];
        fft_serial<32, false>(v, tw32);
#pragma unroll
        for (int n = 0; n < 32; n++) S[lane * 33 + brevn(n, 5)] = v[n];
        __syncwarp();

#pragma unroll
        for (int m = 0; m < 32; m++) v[m] = S[m * 33 + lane];
        fft_serial<32, false>(v, tw32);
#pragma unroll
        for (int m = 0; m < 32; m++) S[brevn(m, 5) * 33 + lane] = v[m];
        __syncwarp();

        // unpack via conjugate symmetry, store both u0f spectra
        {
            const int lnn = (32 - lane) & 31;
            float2* dstA = g_u0f + (bc * 8 + half * 4 + 2 * p) * 1024;
            float2* dstB = dstA + 1024;
#pragma unroll
            for (int m = 0; m < 32; m++) {
                const float2 z1 = S[m * 33 + lane];
                const float2 z2 = S[(((32 - m) & 31)) * 33 + lnn];
                dstA[m * 32 + lane] = make_float2(0.5f * (z1.x + z2.x), 0.5f * (z1.y - z2.y));
                dstB[m * 32 + lane] = make_float2(0.5f * (z1.y + z2.y), 0.5f * (z2.x - z1.x));
            }
        }

        // s1a packed tail: p8 = sub4(Z*phi)
#pragma unroll
        for (int k = 0; k < 2; k++) {
            const int o = lane + 32 * k;
            const int u = o >> 3, vv = o & 7;
            float ar = 0.f, ai = 0.f;
#pragma unroll
            for (int i = 0; i < 4; i++)
#pragma unroll
                for (int j = 0; j < 4; j++) {
                    const float pphi = PHI[(8 * i + u) * 32 + 8 * j + vv];
                    const float2 z = S[(8 * i + u) * 33 + 8 * j + vv];
                    ar = fmaf(z.x, pphi, ar); ai = fmaf(z.y, pphi, ai);
                }
            P8s[p][o] = make_float2(ar * 0.0625f, ai * 0.0625f);
        }
        __syncwarp();

        // separable complex ifft8: row pass
#pragma unroll
        for (int k = 0; k < 2; k++) {
            const int o = lane + 32 * k;
            const int y = o >> 3, vv = o & 7;
            float ar = 0.f, ai = 0.f;
#pragma unroll
            for (int u = 0; u < 8; u++) {
                const float2 pz = P8s[p][u * 8 + vv];
                const float2 w8 = tw8[(y * u) & 7];
                ar = fmaf(pz.x, w8.x, fmaf(-pz.y, w8.y, ar));
                ai = fmaf(pz.y, w8.x, fmaf( pz.x, w8.y, ai));
            }
            R8s[p][o] = make_float2(ar, ai);
        }
        __syncwarp();

        // col pass: Re -> even tile, Im -> odd tile
#pragma unroll
        for (int k = 0; k < 2; k++) {
            const int o = lane + 32 * k;
            const int y = o >> 3, xx = o & 7;
            float ar = 0.f, ai = 0.f;
#pragma unroll
            for (int vv = 0; vv < 8; vv++) {
                const float2 pz = R8s[p][y * 8 + vv];
                const float2 w8 = tw8[(xx * vv) & 7];
                ar = fmaf(pz.x, w8.x, fmaf(-pz.y, w8.y, ar));
                ai = fmaf(pz.y, w8.x, fmaf( pz.x, w8.y, ai));
            }
            float* fb = g_feat + bc * 81 * 64 + (1 + half * 4 + 2 * p) * 64;
            fb[o]      = ar * (1.0f / 64.0f);
            fb[64 + o] = ai * (1.0f / 64.0f);
        }
    }
}

// ---------------- K3: warp-decomposed P16 pipelines (round-12 proven, 7 CTAs/SM) ----------------
__global__ void __launch_bounds__(T128, 7)
k3_p16(const float* __restrict__ psi1, const float* __restrict__ phi) {
    __shared__ float2 Q[8][16 * 17];
    __shared__ float  PHI1[256];
    __shared__ float2 P8W[4][64];
    __shared__ float2 R8W[4][64];
    __shared__ float2 tw16[16];
    __shared__ float2 tw8[8];
    const int tid = threadIdx.x;
    const int w = tid >> 5, lane = tid & 31;
    const int h = lane >> 4, ln = lane & 15;
    const int bc = blockIdx.x / 9;
    const int role = blockIdx.x - bc * 9;

    const float2* __restrict__ src = (role == 0) ? (g_xf + bc * 1024)
                                                 : (g_u0f + (bc * 8 + role - 1) * 1024);
    const int chbase = (role == 0) ? 9 : 17 + (role - 1) * 8;

    if (tid < 16) { float s, c; sincospif((float)tid * 0.125f, &s, &c); tw16[tid] = make_float2(c, s); }
    else if (tid < 24) { const int j = tid - 16; float s, c; sincospif((float)j * 0.25f, &s, &c); tw8[j] = make_float2(c, s); }

#pragma unroll
    for (int k = 0; k < 2; k++) {
        const int idx = tid + 128 * k;
        const int a = idx >> 4, b2 = idx & 15;
        PHI1[idx] = 0.25f * (phi[a * 32 + b2] + phi[(a + 16) * 32 + b2] +
                             phi[a * 32 + b2 + 16] + phi[(a + 16) * 32 + b2 + 16]);
    }

    // Stage A (block-wide, output-stationary over the 8 psi tiles)
#pragma unroll
    for (int k = 0; k < 2; k++) {
        const int e = tid + 128 * k;
        const int a = e >> 4, b2 = e & 15;
        const int o00 = a * 32 + b2;
        const float2 z00 = src[o00],       z01 = src[o00 + 16];
        const float2 z10 = src[o00 + 512], z11 = src[o00 + 528];
#pragma unroll
        for (int t = 0; t < 8; t++) {
            const float* ps = psi1 + t * 1024;
            const float p00 = ps[o00],       p01 = ps[o00 + 16];
            const float p10 = ps[o00 + 512], p11 = ps[o00 + 528];
            float ar = fmaf(z00.x, p00, fmaf(z01.x, p01, fmaf(z10.x, p10, z11.x * p11)));
            float ai = fmaf(z00.y, p00, fmaf(z01.y, p01, fmaf(z10.y, p10, z11.y * p11)));
            Q[t][a * 17 + b2] = make_float2(0.25f * ar, 0.25f * ai);
        }
    }
    __syncthreads();     // the ONLY block barrier

    float2 v[16];
    const int tb = 2 * w + h;
    float2* const QT = Q[tb];
    float2* const UPW = Q[2 * w];
    float* const upf = (float*)UPW;

    // Stage B: rows inverse
#pragma unroll
    for (int n = 0; n < 16; n++) v[n] = QT[ln * 17 + n];
    fft_serial<16, true>(v, tw16);
#pragma unroll
    for (int n = 0; n < 16; n++) QT[ln * 17 + brevn(n, 4)] = v[n];
    __syncwarp();

    // Stage C: cols inverse + modulus; packed write into UPW
#pragma unroll
    for (int m = 0; m < 16; m++) v[m] = QT[m * 17 + ln];
    __syncwarp();
    fft_serial<16, true>(v, tw16);
#pragma unroll
    for (int m = 0; m < 16; m++) {
        const float u = sqrtf(v[m].x * v[m].x + v[m].y * v[m].y) * (1.0f / 256.0f);
        upf[(brevn(m, 4) * 17 + ln) * 2 + h] = u;
    }
    __syncwarp();

    // Stage D: rows fwd on packed u (lanes 0-15)
    if (h == 0) {
#pragma unroll
        for (int n = 0; n < 16; n++) v[n] = UPW[ln * 17 + n];
        fft_serial<16, false>(v, tw16);
#pragma unroll
        for (int n = 0; n < 16; n++) UPW[ln * 17 + brevn(n, 4)] = v[n];
    }
    __syncwarp();

    // Stage E: cols fwd
    if (h == 0) {
#pragma unroll
        for (int m = 0; m < 16; m++) v[m] = UPW[m * 17 + ln];
        fft_serial<16, false>(v, tw16);
#pragma unroll
        for (int m = 0; m < 16; m++) UPW[brevn(m, 4) * 17 + ln] = v[m];
    }
    __syncwarp();

    // Stage F: p8 = sub2(Zpacked * phi1)
#pragma unroll
    for (int k = 0; k < 2; k++) {
        const int o = lane + 32 * k;
        const int u = o >> 3, vv = o & 7;
        float ar = 0.f, ai = 0.f;
#pragma unroll
        for (int i = 0; i < 2; i++)
#pragma unroll
            for (int j = 0; j < 2; j++) {
                const float p = PHI1[(8 * i + u) * 16 + 8 * j + vv];
                const float2 z = UPW[(8 * i + u) * 17 + 8 * j + vv];
                ar = fmaf(z.x, p, ar); ai = fmaf(z.y, p, ai);
            }
        P8W[w][o] = make_float2(0.25f * ar, 0.25f * ai);
    }
    __syncwarp();

    // Stage G1: separable ifft8 — row pass
#pragma unroll
    for (int k = 0; k < 2; k++) {
        const int o = lane + 32 * k;
        const int y = o >> 3, vv = o & 7;
        float ar = 0.f, ai = 0.f;
#pragma unroll
        for (int u = 0; u < 8; u++) {
            const float2 p = P8W[w][u * 8 + vv];
            const float2 w8 = tw8[(y * u) & 7];
            ar = fmaf(p.x, w8.x, fmaf(-p.y, w8.y, ar));
            ai = fmaf(p.y, w8.x, fmaf( p.x, w8.y, ai));
        }
        R8W[w][o] = make_float2(ar, ai);
    }
    __syncwarp();

    // Stage G2: col pass; Re -> chbase+2w, Im -> chbase+2w+1
    float* fb = g_feat + bc * 81 * 64;
#pragma unroll
    for (int k = 0; k < 2; k++) {
        const int o = lane + 32 * k;
        const int y = o >> 3, xx = o & 7;
        float ar = 0.f, ai = 0.f;
#pragma unroll
        for (int vv = 0; vv < 8; vv++) {
            const float2 p = R8W[w][y * 8 + vv];
            const float2 w8 = tw8[(xx * vv) & 7];
            ar = fmaf(p.x, w8.x, fmaf(-p.y, w8.y, ar));
            ai = fmaf(p.y, w8.x, fmaf( p.x, w8.y, ai));
        }
        fb[(chbase + 2 * w)     * 64 + o] = ar * (1.0f / 64.0f);
        fb[(chbase + 2 * w + 1) * 64 + o] = ai * (1.0f / 64.0f);
    }
}

// ---------------- K4: fused stats/GEMV, float4-vectorized (round-12 proven) ----------------
__global__ void __launch_bounds__(T256)
k4_gemv(const float* __restrict__ gamma, const float* __restrict__ beta,
        const float* __restrict__ W, float* __restrict__ out) {
    const int b = blockIdx.x / 9, c = blockIdx.x - (blockIdx.x / 9) * 9;
    const float* f = g_feat + b * 15552 + c * 1728;   // 3 complete groups of 576
    __shared__ float smu[3], srs[3];
    __shared__ float redA[3][2], redB[3][2];
    __shared__ float sA[27], sB[27];
    const int tid = threadIdx.x;

    if (tid < 192) {
        const int g = tid >> 6, l = tid & 63;
        const float4* fg4 = (const float4*)(f + g * 576);   // 144 float4 per group
        float s = 0.f, s2 = 0.f;
#pragma unroll
        for (int it = 0; it < 3; it++) {
            const int i4 = l + 64 * it;
            if (i4 < 144) {
                const float4 xv = fg4[i4];
                s += xv.x + xv.y + xv.z + xv.w;
                s2 = fmaf(xv.x, xv.x, fmaf(xv.y, xv.y, fmaf(xv.z, xv.z, fmaf(xv.w, xv.w, s2))));
            }
        }
#pragma unroll
        for (int o = 16; o > 0; o >>= 1) {
            s  += __shfl_xor_sync(0xffffffffu, s,  o);
            s2 += __shfl_xor_sync(0xffffffffu, s2, o);
        }
        if ((l & 31) == 0) { redA[g][l >> 5] = s; redB[g][l >> 5] = s2; }
    }
    __syncthreads();
    if (tid < 3) {
        const float s = redA[tid][0] + redA[tid][1];
        const float s2 = redB[tid][0] + redB[tid][1];
        const float m = s * (1.0f / 576.0f);
        smu[tid] = m;
        srs[tid] = rsqrtf(s2 * (1.0f / 576.0f) - m * m + 1e-5f);
    }
    __syncthreads();
    if (tid < 27) {
        const int gl = tid / 9;
        const int ch = c * 27 + tid;
        const float a = srs[gl] * gamma[ch];
        sA[tid] = a;
        sB[tid] = beta[ch] - smu[gl] * a;
    }
    __syncthreads();

    float acc[10];
#pragma unroll
    for (int j = 0; j < 10; j++) acc[j] = 0.f;
    const float4* __restrict__ f4 = (const float4*)f;
    const float4* __restrict__ W4 = (const float4*)(W + c * 1728);
#pragma unroll
    for (int it = 0; it < 2; it++) {
        const int i4 = tid + T256 * it;
        if (i4 < 432) {
            const int ch = i4 >> 4;
            const float a = sA[ch], bb = sB[ch];
            const float4 fv = f4[i4];
            float4 nv;
            nv.x = fmaf(fv.x, a, bb);
            nv.y = fmaf(fv.y, a, bb);
            nv.z = fmaf(fv.z, a, bb);
            nv.w = fmaf(fv.w, a, bb);
#pragma unroll
            for (int j = 0; j < 10; j++) {
                const float4 wv = W4[j * 3888 + i4];
                acc[j] = fmaf(nv.x, wv.x,
                         fmaf(nv.y, wv.y,
                         fmaf(nv.z, wv.z,
                         fmaf(nv.w, wv.w, acc[j]))));
            }
        }
    }

    __shared__ float red[8][10];
    const int lane = tid & 31, wrp = tid >> 5;
#pragma unroll
    for (int j = 0; j < 10; j++) {
        float vv = acc[j];
#pragma unroll
        for (int o = 16; o > 0; o >>= 1) vv += __shfl_xor_sync(0xffffffffu, vv, o);
        if (lane == 0) red[wrp][j] = vv;
    }
    __syncthreads();
    if (tid < 10) {
        float vv = 0.f;
#pragma unroll
        for (int w = 0; w < 8; w++) vv += red[w][tid];
        atomicAdd(&out[b * 10 + tid], vv);
    }
}

// ---------------- launch ----------------
extern "C" void kernel_launch(void* const* d_in, const int* in_sizes, int n_in,
                              void* d_out, int out_size) {
    const float* x     = (const float*)d_in[0];
    const float* psi0  = (const float*)d_in[1];
    const float* psi1  = (const float*)d_in[2];
    const float* phi   = (const float*)d_in[3];
    const float* gamma = (const float*)d_in[4];
    const float* beta  = (const float*)d_in[5];
    const float* W     = (const float*)d_in[6];
    const float* bias  = (const float*)d_in[7];
    float* out = (float*)d_out;

    k2_u0f <<<384,      T128>>>(x, psi0, phi, bias, out);
    k3_p16 <<<192 * 9,  T128>>>(psi1, phi);
    k4_gemv<<<64 * 9,   T256>>>(gamma, beta, W, out);
}